// round 11
// baseline (speedup 1.0000x reference)
#include <cuda_runtime.h>
#include <cuda_fp16.h>

// Problem dims: N=50000 nodes, E=800000 edges, in_dim=128, out_dim=64.
#define MAX_N   50176
#define MAX_E   803840
#define IN_DIM  128
#define OUT_DIM 64
#define NEG_SLOPE 0.2f

// Scratch (allocation-free: __device__ globals; zero-initialized at load).
__device__ __half2 g_hh2[MAX_N * (OUT_DIM / 2)];  // h [N,64] as half2
__device__ float g_hs[MAX_N];            // h @ a_src (fp32)
__device__ float g_hd[MAX_N];            // h @ a_dst (fp32)
__device__ int   g_deg[MAX_N];           // out-degree by src (zeroed by k_agg of prior call)
__device__ int   g_rowptr[MAX_N];        // CSR row pointers (exclusive scan)
__device__ int   g_cursor[MAX_N];        // scatter cursors
__device__ int   g_csrdst[MAX_E];        // dst ids grouped by src
// decoupled-lookback scan state (flags zeroed by k_scatter of prior call)
__device__ volatile int g_blockagg[256];
__device__ volatile int g_blockpre[256];
__device__ volatile int g_flag[256];     // 0=none, 1=aggregate, 2=prefix

// ---------------------------------------------------------------------------
// K0: histogram of src (int4-vectorized; g_deg pre-zeroed by prior k_agg)
// ---------------------------------------------------------------------------
__global__ void k_hist(const int* __restrict__ edge, int E) {
    int base = (blockIdx.x * blockDim.x + threadIdx.x) * 4;
    if (base + 3 < E) {
        int4 e = *(const int4*)(edge + base);
        atomicAdd(&g_deg[e.x], 1);
        atomicAdd(&g_deg[e.y], 1);
        atomicAdd(&g_deg[e.z], 1);
        atomicAdd(&g_deg[e.w], 1);
    } else {
        for (int i = base; i < E; i++) atomicAdd(&g_deg[edge[i]], 1);
    }
}

// ---------------------------------------------------------------------------
// K1: h = X @ W, tiled: block = 128 rows x 64 cols, thread = 8 rows x 4 cols.
//     h stored as half2; fused hs/hd projections (fp32).
// ---------------------------------------------------------------------------
#define AS_STRIDE 132
__global__ __launch_bounds__(256) void k_gemm(const float* __restrict__ inp,
                                              const float* __restrict__ Wg,
                                              const float* __restrict__ ag,
                                              int N) {
    __shared__ float Ws[IN_DIM * OUT_DIM];      // W[k][col], 32 KB
    __shared__ float As[16 * AS_STRIDE];        // A-chunk transposed [k][row]
    __shared__ float a_s[OUT_DIM], a_d[OUT_DIM];

    int tid = threadIdx.x;
    {
        const float4* src4 = (const float4*)Wg;
        float4* dst4 = (float4*)Ws;
        for (int i = tid; i < IN_DIM * OUT_DIM / 4; i += 256) dst4[i] = src4[i];
    }
    if (tid < OUT_DIM) {
        a_s[tid] = ag[tid];
        a_d[tid] = ag[OUT_DIM + tid];
    }

    int c = tid & 15;          // col group: cols c*4 .. c*4+3
    int r = tid >> 4;          // row group: rows r*8 .. r*8+7
    int row0 = blockIdx.x * 128;

    float acc[8][4];
#pragma unroll
    for (int i = 0; i < 8; i++)
#pragma unroll
        for (int j = 0; j < 4; j++) acc[i][j] = 0.0f;

    int lrow0 = tid >> 2;            // 0..63
    int lkp   = tid & 3;             // 0..3

#pragma unroll 1
    for (int kc = 0; kc < 8; kc++) {
        __syncthreads();
#pragma unroll
        for (int half = 0; half < 2; half++) {
            int row = lrow0 + half * 64;
            int grow = row0 + row;
            float4 av = (grow < N)
                ? *(const float4*)(inp + (size_t)grow * IN_DIM + kc * 16 + lkp * 4)
                : make_float4(0.f, 0.f, 0.f, 0.f);
            int kb = lkp * 4;
            As[(kb + 0) * AS_STRIDE + row] = av.x;
            As[(kb + 1) * AS_STRIDE + row] = av.y;
            As[(kb + 2) * AS_STRIDE + row] = av.z;
            As[(kb + 3) * AS_STRIDE + row] = av.w;
        }
        __syncthreads();

#pragma unroll
        for (int kk = 0; kk < 16; kk++) {
            int kg = kc * 16 + kk;
            float4 w = *(const float4*)(Ws + kg * OUT_DIM + c * 4);
            float4 aLo = *(const float4*)(As + kk * AS_STRIDE + r * 8);
            float4 aHi = *(const float4*)(As + kk * AS_STRIDE + r * 8 + 4);
            float a[8] = {aLo.x, aLo.y, aLo.z, aLo.w, aHi.x, aHi.y, aHi.z, aHi.w};
#pragma unroll
            for (int i = 0; i < 8; i++) {
                acc[i][0] = fmaf(a[i], w.x, acc[i][0]);
                acc[i][1] = fmaf(a[i], w.y, acc[i][1]);
                acc[i][2] = fmaf(a[i], w.z, acc[i][2]);
                acc[i][3] = fmaf(a[i], w.w, acc[i][3]);
            }
        }
    }

    // write h as half2 pairs
#pragma unroll
    for (int i = 0; i < 8; i++) {
        int grow = row0 + r * 8 + i;
        if (grow < N) {
            __half2* dst = g_hh2 + (size_t)grow * 32 + c * 2;
            dst[0] = __floats2half2_rn(acc[i][0], acc[i][1]);
            dst[1] = __floats2half2_rn(acc[i][2], acc[i][3]);
        }
    }

    // hs/hd projections, reduced across the 16 col-groups
    float4 asv = *(const float4*)(a_s + c * 4);
    float4 adv = *(const float4*)(a_d + c * 4);
#pragma unroll
    for (int i = 0; i < 8; i++) {
        float ps = acc[i][0] * asv.x + acc[i][1] * asv.y +
                   acc[i][2] * asv.z + acc[i][3] * asv.w;
        float pd = acc[i][0] * adv.x + acc[i][1] * adv.y +
                   acc[i][2] * adv.z + acc[i][3] * adv.w;
#pragma unroll
        for (int o = 8; o > 0; o >>= 1) {
            ps += __shfl_xor_sync(0xffffffffu, ps, o);
            pd += __shfl_xor_sync(0xffffffffu, pd, o);
        }
        int grow = row0 + r * 8 + i;
        if (c == 0 && grow < N) {
            g_hs[grow] = ps;
            g_hd[grow] = pd;
        }
    }
}

// ---------------------------------------------------------------------------
// K2: single-pass exclusive scan of g_deg -> rowptr/cursor (decoupled lookback)
// ---------------------------------------------------------------------------
__global__ __launch_bounds__(256) void k_scan(int N) {
    __shared__ int wsum[8];
    __shared__ int s_base;
    int t = threadIdx.x, b = blockIdx.x;
    int lane = t & 31, w = t >> 5;
    int i = b * 256 + t;
    int v = (i < N) ? g_deg[i] : 0;

    int inc = v;
#pragma unroll
    for (int o = 1; o < 32; o <<= 1) {
        int u = __shfl_up_sync(0xffffffffu, inc, o);
        if (lane >= o) inc += u;
    }
    if (lane == 31) wsum[w] = inc;
    __syncthreads();
    if (w == 0) {
        int ws = (lane < 8) ? wsum[lane] : 0;
#pragma unroll
        for (int o = 1; o < 8; o <<= 1) {
            int u = __shfl_up_sync(0xffffffffu, ws, o);
            if (lane >= o) ws += u;
        }
        if (lane < 8) wsum[lane] = ws;
    }
    __syncthreads();
    int wbase = (w > 0) ? wsum[w - 1] : 0;
    int incl  = wbase + inc;
    int total = wsum[7];

    if (t == 0) {
        if (b == 0) {
            g_blockpre[0] = total;
            __threadfence();
            g_flag[0] = 2;
            s_base = 0;
        } else {
            g_blockagg[b] = total;
            __threadfence();
            g_flag[b] = 1;
            int base = 0;
            for (int j = b - 1; j >= 0; j--) {
                int f;
                while ((f = g_flag[j]) == 0) { }
                if (f == 2) { base += g_blockpre[j]; break; }
                base += g_blockagg[j];
            }
            g_blockpre[b] = base + total;
            __threadfence();
            g_flag[b] = 2;
            s_base = base;
        }
    }
    __syncthreads();

    if (i < N) {
        int p = s_base + incl - v;
        g_rowptr[i] = p;
        g_cursor[i] = p;
    }
}

// ---------------------------------------------------------------------------
// K3: scatter dst into CSR buckets (2 edges/thread); block 0 resets scan flags.
// ---------------------------------------------------------------------------
__global__ void k_scatter(const int* __restrict__ edge, int E) {
    if (blockIdx.x == 0) g_flag[threadIdx.x] = 0;
    int i0 = (blockIdx.x * blockDim.x + threadIdx.x) * 2;
#pragma unroll
    for (int u = 0; u < 2; u++) {
        int i = i0 + u;
        if (i < E) {
            int s = edge[i];
            int d = edge[E + i];
            int pos = atomicAdd(&g_cursor[s], 1);
            g_csrdst[pos] = d;
        }
    }
}

// ---------------------------------------------------------------------------
// K4: fused aggregate + softmax + ELU. One warp per node; 2 edges per inner
// step: lanes 0-15 handle edge 2j, lanes 16-31 edge 2j+1; each lane gathers
// uint2 (4 halves = its 4 output dims). Halves combined via shfl_xor(16).
// Also resets g_deg for next call.
// No max-shift: scores bounded, exp safe in fp32; softmax shift-invariant.
// ---------------------------------------------------------------------------
__global__ __launch_bounds__(256) void k_agg(float* __restrict__ out, int N, int E) {
    int gwarp = (blockIdx.x * blockDim.x + threadIdx.x) >> 5;
    if (gwarp >= N) return;
    int lane = threadIdx.x & 31;

    if (lane == 0) g_deg[gwarp] = 0;   // reset for next call

    int start = g_rowptr[gwarp];
    int end   = (gwarp + 1 < N) ? g_rowptr[gwarp + 1] : E;
    float hs_n = g_hs[gwarp];

    int sub = lane >> 4;                 // which edge of the pair
    int lq  = lane & 15;                 // quad: owns dims 4lq..4lq+3
    const __half2* hbase = g_hh2 + lq * 2;

    float a0 = 0.f, a1 = 0.f, a2 = 0.f, a3 = 0.f, spart = 0.f;

    for (int base = start; base < end; base += 32) {
        int i = base + lane;
        bool act = (i < end);
        int dst = act ? g_csrdst[i] : 0;          // coalesced
        float hdv = act ? g_hd[dst] : 0.0f;       // parallel gather
        float sc = hs_n + hdv;
        sc = sc > 0.0f ? sc : NEG_SLOPE * sc;
        float ex = act ? __expf(sc) : 0.0f;
        spart += ex;
        int off = dst * 32;                        // half2-row index

        int cnt = min(32, end - base);
        int steps = (cnt + 1) >> 1;
#pragma unroll 4
        for (int j = 0; j < steps; j++) {
            int e = 2 * j + sub;                   // e==cnt (odd tail) -> ex=0, safe
            float exj = __shfl_sync(0xffffffffu, ex, e);
            int offj  = __shfl_sync(0xffffffffu, off, e);
            uint2 raw = *(const uint2*)(hbase + offj);
            float2 v0 = __half22float2(*(__half2*)&raw.x);
            float2 v1 = __half22float2(*(__half2*)&raw.y);
            a0 = fmaf(exj, v0.x, a0);
            a1 = fmaf(exj, v0.y, a1);
            a2 = fmaf(exj, v1.x, a2);
            a3 = fmaf(exj, v1.y, a3);
        }
    }

    // combine the two edge-halves (each lane pair lq/lq+16 owns same dims)
    a0 += __shfl_xor_sync(0xffffffffu, a0, 16);
    a1 += __shfl_xor_sync(0xffffffffu, a1, 16);
    a2 += __shfl_xor_sync(0xffffffffu, a2, 16);
    a3 += __shfl_xor_sync(0xffffffffu, a3, 16);
#pragma unroll
    for (int o = 16; o > 0; o >>= 1)
        spart += __shfl_xor_sync(0xffffffffu, spart, o);

    if (sub == 0) {
        float4 r;
        if (spart > 0.0f) {
            float inv = 1.0f / spart;
            r.x = a0 * inv; r.y = a1 * inv; r.z = a2 * inv; r.w = a3 * inv;
        } else {
            r.x = r.y = r.z = r.w = 0.0f;
        }
        r.x = r.x > 0.0f ? r.x : expm1f(r.x);
        r.y = r.y > 0.0f ? r.y : expm1f(r.y);
        r.z = r.z > 0.0f ? r.z : expm1f(r.z);
        r.w = r.w > 0.0f ? r.w : expm1f(r.w);
        *(float4*)(out + (size_t)gwarp * OUT_DIM + lq * 4) = r;
    }
}

// ---------------------------------------------------------------------------
// Launch: fork-join graph.
//   main: hist ──► gemm ─────────────────┐
//            └─► s2: scan ─► scatter ────┴─► agg
// Streams/events created per call (cheap; never freed -> stay valid for the
// instantiated graph; no device memory involved).
// ---------------------------------------------------------------------------
extern "C" void kernel_launch(void* const* d_in, const int* in_sizes, int n_in,
                              void* d_out, int out_size) {
    const float* inp  = (const float*)d_in[0];
    const int*   edge = (const int*)d_in[1];
    const float* Wg   = (const float*)d_in[2];
    const float* ag   = (const float*)d_in[3];
    float*       out  = (float*)d_out;

    int N = in_sizes[0] / IN_DIM;
    int E = in_sizes[1] / 2;
    int nchunks = (N + 255) / 256;   // <= 256 required (N <= 65536)

    cudaStream_t s2;
    cudaStreamCreateWithFlags(&s2, cudaStreamNonBlocking);
    cudaEvent_t evA, evB;
    cudaEventCreateWithFlags(&evA, cudaEventDisableTiming);
    cudaEventCreateWithFlags(&evB, cudaEventDisableTiming);

    // main stream: histogram first (CSR branch root)
    k_hist<<<(E / 4 + 255) / 256, 256>>>(edge, E);

    // fork: s2 builds CSR while main runs the GEMM
    cudaEventRecord(evA, 0);
    cudaStreamWaitEvent(s2, evA, 0);
    k_scan   <<<nchunks, 256, 0, s2>>>(N);
    k_scatter<<<(E / 2 + 255) / 256, 256, 0, s2>>>(edge, E);
    cudaEventRecord(evB, s2);

    k_gemm<<<(N + 127) / 128, 256>>>(inp, Wg, ag, N);

    // join: agg needs gemm (stream order) + CSR (event)
    cudaStreamWaitEvent(0, evB, 0);
    k_agg<<<(N + 7) / 8, 256>>>(out, N, E);
}